// round 13
// baseline (speedup 1.0000x reference)
#include <cuda_runtime.h>
#include <cuda_bf16.h>
#include <cstdint>

#define BB 32
#define NN 2000
#define HH 32
#define LL 10

// ---------------- scratch (__device__ globals: allocation-free rule) --------
// X operands stored TRANSPOSED: [b][h][j]  (h-major rows of length NN)
__device__ __align__(16) __nv_bfloat16 g_X1h[BB * HH * NN];
__device__ __align__(16) __nv_bfloat16 g_X1l[BB * HH * NN];
__device__ __align__(16) __nv_bfloat16 g_X2h[BB * HH * NN];
__device__ __align__(16) __nv_bfloat16 g_X2l[BB * HH * NN];
__device__ float g_s[BB * NN];

// ---------------- helpers ---------------------------------------------------
__device__ __forceinline__ uint32_t pack_bf2(float a, float b) {
    uint32_t r;  // a -> low half, b -> high half
    asm("cvt.rn.bf16x2.f32 %0, %1, %2;" : "=r"(r) : "f"(b), "f"(a));
    return r;
}
__device__ __forceinline__ void split2(float x, float y, uint32_t& hi, uint32_t& lo) {
    hi = pack_bf2(x, y);
    lo = pack_bf2(x - __uint_as_float(hi << 16),
                  y - __uint_as_float(hi & 0xffff0000u));
}
__device__ __forceinline__ void mma16816(float* c, const uint32_t* a, const uint32_t* b) {
    asm volatile(
        "mma.sync.aligned.m16n8k16.row.col.f32.bf16.bf16.f32 "
        "{%0,%1,%2,%3}, {%4,%5,%6,%7}, {%8,%9}, {%0,%1,%2,%3};"
        : "+f"(c[0]), "+f"(c[1]), "+f"(c[2]), "+f"(c[3])
        : "r"(a[0]), "r"(a[1]), "r"(a[2]), "r"(a[3]), "r"(b[0]), "r"(b[1]));
}

// ---------------------------------------------------------------------------
// k_prep: O = X @ W (fp32 32x32), split to bf16 hi/lo, stored TRANSPOSED
// [by][h][j]. Grid (32, BB): block = 64 rows of one batch.
// ---------------------------------------------------------------------------
__global__ __launch_bounds__(256) void k_prep(const float* __restrict__ X,
                                              const float* __restrict__ W,
                                              __nv_bfloat16* __restrict__ Oh,
                                              __nv_bfloat16* __restrict__ Ol) {
    __shared__ float Ws[32][32];
    __shared__ float Vs[64][32];
    int tid = threadIdx.x;
    int by = blockIdx.y;
    int j0 = blockIdx.x * 64;
    {
        int idx = tid * 4;
        *(float4*)&Ws[idx >> 5][idx & 31] = *(const float4*)&W[idx];
    }
    #pragma unroll
    for (int q = 0; q < 2; q++) {
        int t = tid + q * 256;
        int r = t >> 3, c4 = t & 7;
        float4 v = make_float4(0.f, 0.f, 0.f, 0.f);
        if (j0 + r < NN)
            v = *(const float4*)&X[((size_t)by * NN + j0 + r) * 32 + c4 * 4];
        *(float4*)&Vs[r][c4 * 4] = v;
    }
    __syncthreads();

    int h = tid & 31;
    int rg = tid >> 5;
    float acc[8];
    #pragma unroll
    for (int r = 0; r < 8; r++) acc[r] = 0.f;
    #pragma unroll 8
    for (int k = 0; k < 32; k++) {
        float w = Ws[k][h];
        #pragma unroll
        for (int r = 0; r < 8; r++) acc[r] += Vs[rg * 8 + r][k] * w;
    }
    if (j0 + rg * 8 < NN) {
        uint4 hv, lv;
        split2(acc[0], acc[1], hv.x, lv.x);
        split2(acc[2], acc[3], hv.y, lv.y);
        split2(acc[4], acc[5], hv.z, lv.z);
        split2(acc[6], acc[7], hv.w, lv.w);
        size_t o = (size_t)by * HH * NN + (size_t)h * NN + j0 + rg * 8;
        *(uint4*)(Oh + o) = hv;
        *(uint4*)(Ol + o) = lv;
    }
}

// ---------------------------------------------------------------------------
// k_gcn: C = relu(adj @ X) via mma.sync split-precision bf16.
// Mainloop = R7 structure (measured 139.6us/layer): adj LDGs inside ks steps
// (warps drift and cover each other's latency), single-buffer X smem.
//   L1=true : epilogue fuses X2 = relu(C) @ W2, split->bf16, transposed store.
//   L1=false: epilogue writes sum_h relu(C) to s.
// CTA: 128 rows x 32 cols; 8 warps, each m16 x n32. K chunks of 64.
// ---------------------------------------------------------------------------
#define XS_STRIDE 72  // elements; 144B row stride -> conflict-free LDS + STS

template <bool L1>
__global__ __launch_bounds__(256) void k_gcn(const float* __restrict__ adj,
                                             const __nv_bfloat16* __restrict__ Xth,
                                             const __nv_bfloat16* __restrict__ Xtl,
                                             const float* __restrict__ W2,
                                             __nv_bfloat16* __restrict__ Oh,
                                             __nv_bfloat16* __restrict__ Ol,
                                             float* __restrict__ s) {
    __shared__ __nv_bfloat16 Xs[2][32][XS_STRIDE];
    __shared__ float W2s[32][32];     // referenced only when L1
    __shared__ float Yst[8][16][33];  // referenced only when L1

    int tid = threadIdx.x, wid = tid >> 5, lane = tid & 31;
    int lq = lane & 3, lg = lane >> 2;
    int b = blockIdx.y;
    int i0 = blockIdx.x * 128;

    if (L1) {
        int idx = tid * 4;
        *(float4*)&W2s[idx >> 5][idx & 31] = *(const float4*)&W2[idx];
    }

    const float* __restrict__ adjb = adj + (size_t)b * NN * NN;
    const __nv_bfloat16* __restrict__ Xh = Xth + (size_t)b * HH * NN;
    const __nv_bfloat16* __restrict__ Xl = Xtl + (size_t)b * HH * NN;

    int mr0 = i0 + wid * 16 + lg;
    int mr1 = mr0 + 8;
    bool rv0 = mr0 < NN, rv1 = mr1 < NN;
    const float* __restrict__ ar0 = adjb + (size_t)mr0 * NN;
    const float* __restrict__ ar1 = adjb + (size_t)mr1 * NN;

    float acc[4][4];
    #pragma unroll
    for (int nt = 0; nt < 4; nt++)
        #pragma unroll
        for (int e = 0; e < 4; e++) acc[nt][e] = 0.f;

    int bh_ = tid >> 3;   // X smem load: h row 0..31
    int bseg = tid & 7;   // 8-elem segment along j

    const float2 z2 = make_float2(0.f, 0.f);

    for (int c = 0; c < 32; c++) {
        int j0 = c * 64;
        __syncthreads();  // WAR: previous chunk's LDS done before overwrite
        {   // load X chunk [32 h][64 j] hi+lo into smem (uint4, conflict-free)
            int j = j0 + bseg * 8;
            uint4 vh = make_uint4(0, 0, 0, 0), vl = make_uint4(0, 0, 0, 0);
            if (j + 8 <= NN) {
                size_t o = (size_t)bh_ * NN + j;
                vh = __ldg((const uint4*)(Xh + o));
                vl = __ldg((const uint4*)(Xl + o));
            }
            *(uint4*)&Xs[0][bh_][bseg * 8] = vh;
            *(uint4*)&Xs[1][bh_][bseg * 8] = vl;
        }
        __syncthreads();

        if (j0 + 64 <= NN) {
            #pragma unroll
            for (int ks = 0; ks < 4; ks++) {
                int ca = j0 + ks * 16 + lq * 2;
                uint32_t ah[4], al[4];
                float2 f;
                f = rv0 ? __ldg((const float2*)(ar0 + ca)) : z2;
                split2(f.x, f.y, ah[0], al[0]);
                f = rv1 ? __ldg((const float2*)(ar1 + ca)) : z2;
                split2(f.x, f.y, ah[1], al[1]);
                f = rv0 ? __ldg((const float2*)(ar0 + ca + 8)) : z2;
                split2(f.x, f.y, ah[2], al[2]);
                f = rv1 ? __ldg((const float2*)(ar1 + ca + 8)) : z2;
                split2(f.x, f.y, ah[3], al[3]);

                int kk = ks * 16 + lq * 2;
                #pragma unroll
                for (int nt = 0; nt < 4; nt++) {
                    int n = nt * 8 + lg;
                    uint32_t bh2[2], bl2[2];
                    bh2[0] = *(const uint32_t*)&Xs[0][n][kk];
                    bh2[1] = *(const uint32_t*)&Xs[0][n][kk + 8];
                    bl2[0] = *(const uint32_t*)&Xs[1][n][kk];
                    bl2[1] = *(const uint32_t*)&Xs[1][n][kk + 8];
                    mma16816(acc[nt], ah, bh2);
                    mma16816(acc[nt], ah, bl2);
                    mma16816(acc[nt], al, bh2);
                }
            }
        } else {
            // last chunk: j0=1984, only k-step 0 (cols 1984..1999) is valid
            int ca = j0 + lq * 2;
            uint32_t ah[4], al[4];
            float2 f;
            f = rv0 ? __ldg((const float2*)(ar0 + ca)) : z2;
            split2(f.x, f.y, ah[0], al[0]);
            f = rv1 ? __ldg((const float2*)(ar1 + ca)) : z2;
            split2(f.x, f.y, ah[1], al[1]);
            f = rv0 ? __ldg((const float2*)(ar0 + ca + 8)) : z2;
            split2(f.x, f.y, ah[2], al[2]);
            f = rv1 ? __ldg((const float2*)(ar1 + ca + 8)) : z2;
            split2(f.x, f.y, ah[3], al[3]);

            int kk = lq * 2;
            #pragma unroll
            for (int nt = 0; nt < 4; nt++) {
                int n = nt * 8 + lg;
                uint32_t bh2[2], bl2[2];
                bh2[0] = *(const uint32_t*)&Xs[0][n][kk];
                bh2[1] = *(const uint32_t*)&Xs[0][n][kk + 8];
                bl2[0] = *(const uint32_t*)&Xs[1][n][kk];
                bl2[1] = *(const uint32_t*)&Xs[1][n][kk + 8];
                mma16816(acc[nt], ah, bh2);
                mma16816(acc[nt], ah, bl2);
                mma16816(acc[nt], al, bh2);
            }
        }
    }

    // ---- epilogue ----
    if (L1) {
        // NN % 16 == 0 -> each warp's 16-row block is fully valid or fully not
        int wbase = i0 + wid * 16;
        #pragma unroll
        for (int nt = 0; nt < 4; nt++) {
            int h0 = nt * 8 + lq * 2;
            Yst[wid][lg][h0]     = fmaxf(acc[nt][0], 0.f);
            Yst[wid][lg][h0 + 1] = fmaxf(acc[nt][1], 0.f);
            Yst[wid][lg + 8][h0]     = fmaxf(acc[nt][2], 0.f);
            Yst[wid][lg + 8][h0 + 1] = fmaxf(acc[nt][3], 0.f);
        }
        __syncwarp();
        if (wbase < NN) {
            float x2[32];
            if (lane < 16) {
                float y[32];
                #pragma unroll
                for (int h = 0; h < 32; h++) y[h] = Yst[wid][lane][h];
                #pragma unroll
                for (int g = 0; g < 32; g++) x2[g] = 0.f;
                #pragma unroll
                for (int h = 0; h < 32; h++) {
                    float yv = y[h];
                    #pragma unroll
                    for (int g = 0; g < 32; g++) x2[g] += yv * W2s[h][g];
                }
            }
            __syncwarp();
            if (lane < 16) {
                #pragma unroll
                for (int g = 0; g < 32; g++) Yst[wid][lane][g] = x2[g];
            }
            __syncwarp();
            {   // transposed split store: lane = h, pack 16 rows as 2x uint4
                int h = lane;
                float v[16];
                #pragma unroll
                for (int r = 0; r < 16; r++) v[r] = Yst[wid][r][h];
                size_t o = (size_t)b * HH * NN + (size_t)h * NN + wbase;
                uint4 hv, lv;
                split2(v[0], v[1], hv.x, lv.x);
                split2(v[2], v[3], hv.y, lv.y);
                split2(v[4], v[5], hv.z, lv.z);
                split2(v[6], v[7], hv.w, lv.w);
                *(uint4*)(Oh + o) = hv;
                *(uint4*)(Ol + o) = lv;
                split2(v[8],  v[9],  hv.x, lv.x);
                split2(v[10], v[11], hv.y, lv.y);
                split2(v[12], v[13], hv.z, lv.z);
                split2(v[14], v[15], hv.w, lv.w);
                *(uint4*)(Oh + o + 8) = hv;
                *(uint4*)(Ol + o + 8) = lv;
            }
        }
    } else {
        float s0 = 0.f, s1 = 0.f;
        #pragma unroll
        for (int nt = 0; nt < 4; nt++) {
            s0 += fmaxf(acc[nt][0], 0.f) + fmaxf(acc[nt][1], 0.f);
            s1 += fmaxf(acc[nt][2], 0.f) + fmaxf(acc[nt][3], 0.f);
        }
        s0 += __shfl_xor_sync(0xffffffffu, s0, 1);
        s0 += __shfl_xor_sync(0xffffffffu, s0, 2);
        s1 += __shfl_xor_sync(0xffffffffu, s1, 1);
        s1 += __shfl_xor_sync(0xffffffffu, s1, 2);
        if (lq == 0) {
            if (rv0) s[(size_t)b * NN + mr0] = s0;
            if (rv1) s[(size_t)b * NN + mr1] = s1;
        }
    }
}

// ---------------------------------------------------------------------------
// k_head: one CTA per (b, l); 128 threads block-reduce the 2000-dot.
// ---------------------------------------------------------------------------
__global__ __launch_bounds__(128) void k_head(const float* __restrict__ s,
                                              const float* __restrict__ out_w,
                                              const float* __restrict__ out_b,
                                              float* __restrict__ out) {
    __shared__ float red[4];
    int b = blockIdx.x / LL;
    int l = blockIdx.x % LL;
    int tid = threadIdx.x, lane = tid & 31, wrp = tid >> 5;
    const float* sb = s + (size_t)b * NN;
    const float* wl = out_w + (size_t)l * NN;
    float acc = 0.f;
    #pragma unroll 4
    for (int i = tid * 4; i < NN; i += 512) {
        float4 a = *(const float4*)(sb + i);
        float4 w = *(const float4*)(wl + i);
        acc += a.x * w.x + a.y * w.y + a.z * w.z + a.w * w.w;
    }
    #pragma unroll
    for (int off = 16; off > 0; off >>= 1)
        acc += __shfl_down_sync(0xffffffffu, acc, off);
    if (lane == 0) red[wrp] = acc;
    __syncthreads();
    if (tid == 0)
        out[b * LL + l] = red[0] + red[1] + red[2] + red[3] + out_b[l];
}

// ---------------------------------------------------------------------------
extern "C" void kernel_launch(void* const* d_in, const int* in_sizes, int n_in,
                              void* d_out, int out_size) {
    const float* v     = (const float*)d_in[0];
    const float* adj   = (const float*)d_in[1];
    const float* W1    = (const float*)d_in[2];
    const float* W2    = (const float*)d_in[3];
    const float* out_w = (const float*)d_in[4];
    const float* out_b = (const float*)d_in[5];
    float* out = (float*)d_out;

    __nv_bfloat16 *pX1h, *pX1l, *pX2h, *pX2l;
    float* ps;
    cudaGetSymbolAddress((void**)&pX1h, g_X1h);
    cudaGetSymbolAddress((void**)&pX1l, g_X1l);
    cudaGetSymbolAddress((void**)&pX2h, g_X2h);
    cudaGetSymbolAddress((void**)&pX2l, g_X2l);
    cudaGetSymbolAddress((void**)&ps, g_s);

    dim3 gridP(32, BB);   // 32 x 64-row tiles per batch
    dim3 gridG(16, BB);   // 16 x 128-row tiles per batch

    k_prep<<<gridP, 256>>>(v, W1, pX1h, pX1l);
    k_gcn<true><<<gridG, 256>>>(adj, pX1h, pX1l, W2, pX2h, pX2l, nullptr);
    k_gcn<false><<<gridG, 256>>>(adj, pX2h, pX2l, nullptr, nullptr, nullptr, ps);
    k_head<<<BB * LL, 128>>>(ps, out_w, out_b, out);
}

// round 14
// speedup vs baseline: 1.2435x; 1.2435x over previous
#include <cuda_runtime.h>
#include <cuda_bf16.h>
#include <cstdint>

#define BB 32
#define NN 2000
#define HH 32
#define LL 10

// ---------------- scratch (__device__ globals: allocation-free rule) --------
// X operands stored TRANSPOSED: [b][h][j]  (h-major rows of length NN)
__device__ __align__(16) __nv_bfloat16 g_X1h[BB * HH * NN];
__device__ __align__(16) __nv_bfloat16 g_X1l[BB * HH * NN];
__device__ __align__(16) __nv_bfloat16 g_X2h[BB * HH * NN];
__device__ __align__(16) __nv_bfloat16 g_X2l[BB * HH * NN];
__device__ float g_s[BB * NN];

// ---------------- helpers ---------------------------------------------------
__device__ __forceinline__ uint32_t pack_bf2(float a, float b) {
    uint32_t r;  // a -> low half, b -> high half
    asm("cvt.rn.bf16x2.f32 %0, %1, %2;" : "=r"(r) : "f"(b), "f"(a));
    return r;
}
__device__ __forceinline__ void split2(float x, float y, uint32_t& hi, uint32_t& lo) {
    hi = pack_bf2(x, y);
    lo = pack_bf2(x - __uint_as_float(hi << 16),
                  y - __uint_as_float(hi & 0xffff0000u));
}
__device__ __forceinline__ void mma16816(float* c, const uint32_t* a, const uint32_t* b) {
    asm volatile(
        "mma.sync.aligned.m16n8k16.row.col.f32.bf16.bf16.f32 "
        "{%0,%1,%2,%3}, {%4,%5,%6,%7}, {%8,%9}, {%0,%1,%2,%3};"
        : "+f"(c[0]), "+f"(c[1]), "+f"(c[2]), "+f"(c[3])
        : "r"(a[0]), "r"(a[1]), "r"(a[2]), "r"(a[3]), "r"(b[0]), "r"(b[1]));
}

// ---------------------------------------------------------------------------
// k_prep: O = X @ W (fp32 32x32), split to bf16 hi/lo, stored TRANSPOSED
// [by][h][j]. Grid (32, BB): block = 64 rows of one batch.
// ---------------------------------------------------------------------------
__global__ __launch_bounds__(256) void k_prep(const float* __restrict__ X,
                                              const float* __restrict__ W,
                                              __nv_bfloat16* __restrict__ Oh,
                                              __nv_bfloat16* __restrict__ Ol) {
    __shared__ float Ws[32][32];
    __shared__ float Vs[64][32];
    int tid = threadIdx.x;
    int by = blockIdx.y;
    int j0 = blockIdx.x * 64;
    {
        int idx = tid * 4;
        *(float4*)&Ws[idx >> 5][idx & 31] = *(const float4*)&W[idx];
    }
    #pragma unroll
    for (int q = 0; q < 2; q++) {
        int t = tid + q * 256;
        int r = t >> 3, c4 = t & 7;
        float4 v = make_float4(0.f, 0.f, 0.f, 0.f);
        if (j0 + r < NN)
            v = *(const float4*)&X[((size_t)by * NN + j0 + r) * 32 + c4 * 4];
        *(float4*)&Vs[r][c4 * 4] = v;
    }
    __syncthreads();

    int h = tid & 31;
    int rg = tid >> 5;
    float acc[8];
    #pragma unroll
    for (int r = 0; r < 8; r++) acc[r] = 0.f;
    #pragma unroll 8
    for (int k = 0; k < 32; k++) {
        float w = Ws[k][h];
        #pragma unroll
        for (int r = 0; r < 8; r++) acc[r] += Vs[rg * 8 + r][k] * w;
    }
    if (j0 + rg * 8 < NN) {
        uint4 hv, lv;
        split2(acc[0], acc[1], hv.x, lv.x);
        split2(acc[2], acc[3], hv.y, lv.y);
        split2(acc[4], acc[5], hv.z, lv.z);
        split2(acc[6], acc[7], hv.w, lv.w);
        size_t o = (size_t)by * HH * NN + (size_t)h * NN + j0 + rg * 8;
        *(uint4*)(Oh + o) = hv;
        *(uint4*)(Ol + o) = lv;
    }
}

// ---------------------------------------------------------------------------
// k_gcn: C = relu(adj @ X) via mma.sync split-precision bf16.
// Mainloop = exact R7 structure (measured 139.6us/layer): plain loads inside
// ks steps (ptxas hoists; warps drift to cover latency), single-buffer Xs.
//   L1=true : low-register fused epilogue: X2 = relu(C) @ W2 computed
//             COLUMN-WISE (lane g -> 16-row column, ~20 live regs), then
//             split->bf16 transposed store straight from the column regs.
//   L1=false: epilogue writes sum_h relu(C) to s (identical to R7).
// CTA: 128 rows x 32 cols; 8 warps, each m16 x n32. K chunks of 64.
// ---------------------------------------------------------------------------
#define XS_STRIDE 72  // elements; 144B row stride -> conflict-free LDS + STS
#define YST_R 33      // Yst row stride (floats)

template <bool L1>
__global__ __launch_bounds__(256) void k_gcn(const float* __restrict__ adj,
                                             const __nv_bfloat16* __restrict__ Xth,
                                             const __nv_bfloat16* __restrict__ Xtl,
                                             const float* __restrict__ W2,
                                             __nv_bfloat16* __restrict__ Oh,
                                             __nv_bfloat16* __restrict__ Ol,
                                             float* __restrict__ s) {
    __shared__ __nv_bfloat16 Xs[2][32][XS_STRIDE];
    __shared__ float W2s[L1 ? 32 * 32 : 1];          // only sized when L1
    __shared__ float Yst[L1 ? 8 * 16 * YST_R : 1];   // per-warp staging (L1)

    int tid = threadIdx.x, wid = tid >> 5, lane = tid & 31;
    int lq = lane & 3, lg = lane >> 2;
    int b = blockIdx.y;
    int i0 = blockIdx.x * 128;

    if (L1) {
        *(float4*)&W2s[tid * 4] = *(const float4*)&W2[tid * 4];
    }

    const float* __restrict__ adjb = adj + (size_t)b * NN * NN;
    const __nv_bfloat16* __restrict__ Xh = Xth + (size_t)b * HH * NN;
    const __nv_bfloat16* __restrict__ Xl = Xtl + (size_t)b * HH * NN;

    int mr0 = i0 + wid * 16 + lg;
    int mr1 = mr0 + 8;
    bool rv0 = mr0 < NN, rv1 = mr1 < NN;
    const float* __restrict__ ar0 = adjb + (size_t)mr0 * NN;
    const float* __restrict__ ar1 = adjb + (size_t)mr1 * NN;

    float acc[4][4];
    #pragma unroll
    for (int nt = 0; nt < 4; nt++)
        #pragma unroll
        for (int e = 0; e < 4; e++) acc[nt][e] = 0.f;

    int bh_ = tid >> 3;   // X smem load: h row 0..31
    int bseg = tid & 7;   // 8-elem segment along j

    const float2 z2 = make_float2(0.f, 0.f);

    for (int c = 0; c < 32; c++) {
        int j0 = c * 64;
        __syncthreads();  // WAR: previous chunk's LDS done before overwrite
        {   // load X chunk [32 h][64 j] hi+lo into smem (uint4, conflict-free)
            int j = j0 + bseg * 8;
            uint4 vh = make_uint4(0, 0, 0, 0), vl = make_uint4(0, 0, 0, 0);
            if (j + 8 <= NN) {
                size_t o = (size_t)bh_ * NN + j;
                vh = *(const uint4*)(Xh + o);
                vl = *(const uint4*)(Xl + o);
            }
            *(uint4*)&Xs[0][bh_][bseg * 8] = vh;
            *(uint4*)&Xs[1][bh_][bseg * 8] = vl;
        }
        __syncthreads();

        if (j0 + 64 <= NN) {
            #pragma unroll
            for (int ks = 0; ks < 4; ks++) {
                int ca = j0 + ks * 16 + lq * 2;
                uint32_t ah[4], al[4];
                float2 f;
                f = rv0 ? *(const float2*)(ar0 + ca) : z2;
                split2(f.x, f.y, ah[0], al[0]);
                f = rv1 ? *(const float2*)(ar1 + ca) : z2;
                split2(f.x, f.y, ah[1], al[1]);
                f = rv0 ? *(const float2*)(ar0 + ca + 8) : z2;
                split2(f.x, f.y, ah[2], al[2]);
                f = rv1 ? *(const float2*)(ar1 + ca + 8) : z2;
                split2(f.x, f.y, ah[3], al[3]);

                int kk = ks * 16 + lq * 2;
                #pragma unroll
                for (int nt = 0; nt < 4; nt++) {
                    int n = nt * 8 + lg;
                    uint32_t bh2[2], bl2[2];
                    bh2[0] = *(const uint32_t*)&Xs[0][n][kk];
                    bh2[1] = *(const uint32_t*)&Xs[0][n][kk + 8];
                    bl2[0] = *(const uint32_t*)&Xs[1][n][kk];
                    bl2[1] = *(const uint32_t*)&Xs[1][n][kk + 8];
                    mma16816(acc[nt], ah, bh2);
                    mma16816(acc[nt], ah, bl2);
                    mma16816(acc[nt], al, bh2);
                }
            }
        } else {
            // last chunk: j0=1984, only k-step 0 (cols 1984..1999) is valid
            int ca = j0 + lq * 2;
            uint32_t ah[4], al[4];
            float2 f;
            f = rv0 ? *(const float2*)(ar0 + ca) : z2;
            split2(f.x, f.y, ah[0], al[0]);
            f = rv1 ? *(const float2*)(ar1 + ca) : z2;
            split2(f.x, f.y, ah[1], al[1]);
            f = rv0 ? *(const float2*)(ar0 + ca + 8) : z2;
            split2(f.x, f.y, ah[2], al[2]);
            f = rv1 ? *(const float2*)(ar1 + ca + 8) : z2;
            split2(f.x, f.y, ah[3], al[3]);

            int kk = lq * 2;
            #pragma unroll
            for (int nt = 0; nt < 4; nt++) {
                int n = nt * 8 + lg;
                uint32_t bh2[2], bl2[2];
                bh2[0] = *(const uint32_t*)&Xs[0][n][kk];
                bh2[1] = *(const uint32_t*)&Xs[0][n][kk + 8];
                bl2[0] = *(const uint32_t*)&Xs[1][n][kk];
                bl2[1] = *(const uint32_t*)&Xs[1][n][kk + 8];
                mma16816(acc[nt], ah, bh2);
                mma16816(acc[nt], ah, bl2);
                mma16816(acc[nt], al, bh2);
            }
        }
    }

    // ---- epilogue ----
    if (L1) {
        // NN % 16 == 0 -> each warp's 16-row block is fully valid or fully not
        int wbase = i0 + wid * 16;
        float* Yw = &Yst[wid * 16 * YST_R];
        #pragma unroll
        for (int nt = 0; nt < 4; nt++) {
            int h0 = nt * 8 + lq * 2;
            Yw[lg * YST_R + h0]           = fmaxf(acc[nt][0], 0.f);
            Yw[lg * YST_R + h0 + 1]       = fmaxf(acc[nt][1], 0.f);
            Yw[(lg + 8) * YST_R + h0]     = fmaxf(acc[nt][2], 0.f);
            Yw[(lg + 8) * YST_R + h0 + 1] = fmaxf(acc[nt][3], 0.f);
        }
        __syncwarp();
        if (wbase < NN) {
            // column-wise: lane g computes x2[0..15][g]; ~20 live registers.
            int g = lane;
            float col[16];
            #pragma unroll
            for (int r = 0; r < 16; r++) col[r] = 0.f;
            #pragma unroll
            for (int h = 0; h < 32; h++) {
                float wv = W2s[h * 32 + g];   // stride-1 across lanes
                #pragma unroll
                for (int r = 0; r < 16; r++)
                    col[r] += Yw[r * YST_R + h] * wv;  // broadcast LDS
            }
            // lane g holds transposed column g: split + store directly
            size_t o = (size_t)b * HH * NN + (size_t)g * NN + wbase;
            uint4 hv, lv;
            split2(col[0], col[1], hv.x, lv.x);
            split2(col[2], col[3], hv.y, lv.y);
            split2(col[4], col[5], hv.z, lv.z);
            split2(col[6], col[7], hv.w, lv.w);
            *(uint4*)(Oh + o) = hv;
            *(uint4*)(Ol + o) = lv;
            split2(col[8],  col[9],  hv.x, lv.x);
            split2(col[10], col[11], hv.y, lv.y);
            split2(col[12], col[13], hv.z, lv.z);
            split2(col[14], col[15], hv.w, lv.w);
            *(uint4*)(Oh + o + 8) = hv;
            *(uint4*)(Ol + o + 8) = lv;
        }
    } else {
        float s0 = 0.f, s1 = 0.f;
        #pragma unroll
        for (int nt = 0; nt < 4; nt++) {
            s0 += fmaxf(acc[nt][0], 0.f) + fmaxf(acc[nt][1], 0.f);
            s1 += fmaxf(acc[nt][2], 0.f) + fmaxf(acc[nt][3], 0.f);
        }
        s0 += __shfl_xor_sync(0xffffffffu, s0, 1);
        s0 += __shfl_xor_sync(0xffffffffu, s0, 2);
        s1 += __shfl_xor_sync(0xffffffffu, s1, 1);
        s1 += __shfl_xor_sync(0xffffffffu, s1, 2);
        if (lq == 0) {
            if (rv0) s[(size_t)b * NN + mr0] = s0;
            if (rv1) s[(size_t)b * NN + mr1] = s1;
        }
    }
}

// ---------------------------------------------------------------------------
// k_head: one CTA per (b, l); 128 threads block-reduce the 2000-dot.
// ---------------------------------------------------------------------------
__global__ __launch_bounds__(128) void k_head(const float* __restrict__ s,
                                              const float* __restrict__ out_w,
                                              const float* __restrict__ out_b,
                                              float* __restrict__ out) {
    __shared__ float red[4];
    int b = blockIdx.x / LL;
    int l = blockIdx.x % LL;
    int tid = threadIdx.x, lane = tid & 31, wrp = tid >> 5;
    const float* sb = s + (size_t)b * NN;
    const float* wl = out_w + (size_t)l * NN;
    float acc = 0.f;
    #pragma unroll 4
    for (int i = tid * 4; i < NN; i += 512) {
        float4 a = *(const float4*)(sb + i);
        float4 w = *(const float4*)(wl + i);
        acc += a.x * w.x + a.y * w.y + a.z * w.z + a.w * w.w;
    }
    #pragma unroll
    for (int off = 16; off > 0; off >>= 1)
        acc += __shfl_down_sync(0xffffffffu, acc, off);
    if (lane == 0) red[wrp] = acc;
    __syncthreads();
    if (tid == 0)
        out[b * LL + l] = red[0] + red[1] + red[2] + red[3] + out_b[l];
}

// ---------------------------------------------------------------------------
extern "C" void kernel_launch(void* const* d_in, const int* in_sizes, int n_in,
                              void* d_out, int out_size) {
    const float* v     = (const float*)d_in[0];
    const float* adj   = (const float*)d_in[1];
    const float* W1    = (const float*)d_in[2];
    const float* W2    = (const float*)d_in[3];
    const float* out_w = (const float*)d_in[4];
    const float* out_b = (const float*)d_in[5];
    float* out = (float*)d_out;

    __nv_bfloat16 *pX1h, *pX1l, *pX2h, *pX2l;
    float* ps;
    cudaGetSymbolAddress((void**)&pX1h, g_X1h);
    cudaGetSymbolAddress((void**)&pX1l, g_X1l);
    cudaGetSymbolAddress((void**)&pX2h, g_X2h);
    cudaGetSymbolAddress((void**)&pX2l, g_X2l);
    cudaGetSymbolAddress((void**)&ps, g_s);

    dim3 gridP(32, BB);   // 32 x 64-row tiles per batch
    dim3 gridG(16, BB);   // 16 x 128-row tiles per batch

    k_prep<<<gridP, 256>>>(v, W1, pX1h, pX1l);
    k_gcn<true><<<gridG, 256>>>(adj, pX1h, pX1l, W2, pX2h, pX2l, nullptr);
    k_gcn<false><<<gridG, 256>>>(adj, pX2h, pX2l, nullptr, nullptr, nullptr, ps);
    k_head<<<BB * LL, 128>>>(ps, out_w, out_b, out);
}

// round 15
// speedup vs baseline: 1.5379x; 1.2368x over previous
#include <cuda_runtime.h>
#include <cuda_bf16.h>
#include <cstdint>

#define BB 32
#define NN 2000
#define HH 32
#define LL 10

// ---------------- scratch (__device__ globals: allocation-free rule) --------
// X operands stored TRANSPOSED: [b][h][j]  (h-major rows of length NN)
__device__ __align__(16) __nv_bfloat16 g_X1h[BB * HH * NN];
__device__ __align__(16) __nv_bfloat16 g_X1l[BB * HH * NN];
__device__ __align__(16) __nv_bfloat16 g_X2h[BB * HH * NN];
__device__ __align__(16) __nv_bfloat16 g_X2l[BB * HH * NN];
__device__ float g_Y1[BB * NN * HH];   // layer-1 relu output, fp32, [b][j][h]
__device__ float g_s[BB * NN];

// ---------------- helpers ---------------------------------------------------
__device__ __forceinline__ uint32_t pack_bf2(float a, float b) {
    uint32_t r;  // a -> low half, b -> high half
    asm("cvt.rn.bf16x2.f32 %0, %1, %2;" : "=r"(r) : "f"(b), "f"(a));
    return r;
}
// split (x,y) fp32 pair into bf16x2 hi + bf16x2 lo (residual)
__device__ __forceinline__ void split2(float x, float y, uint32_t& hi, uint32_t& lo) {
    hi = pack_bf2(x, y);
    lo = pack_bf2(x - __uint_as_float(hi << 16),
                  y - __uint_as_float(hi & 0xffff0000u));
}
// D += A * B   (m16n8k16, bf16 in, fp32 acc) — SIMT HMMA, no arch-a features
__device__ __forceinline__ void mma16816(float* c, const uint32_t* a, const uint32_t* b) {
    asm volatile(
        "mma.sync.aligned.m16n8k16.row.col.f32.bf16.bf16.f32 "
        "{%0,%1,%2,%3}, {%4,%5,%6,%7}, {%8,%9}, {%0,%1,%2,%3};"
        : "+f"(c[0]), "+f"(c[1]), "+f"(c[2]), "+f"(c[3])
        : "r"(a[0]), "r"(a[1]), "r"(a[2]), "r"(a[3]), "r"(b[0]), "r"(b[1]));
}

// ---------------------------------------------------------------------------
// k_prep: O = X @ W (fp32 32x32), split to bf16 hi/lo, stored TRANSPOSED
// [by][h][j]. Grid (32, BB): block = 64 rows of one batch.
// ---------------------------------------------------------------------------
__global__ __launch_bounds__(256) void k_prep(const float* __restrict__ X,
                                              const float* __restrict__ W,
                                              __nv_bfloat16* __restrict__ Oh,
                                              __nv_bfloat16* __restrict__ Ol) {
    __shared__ float Ws[32][32];
    __shared__ float Vs[64][32];
    int tid = threadIdx.x;
    int by = blockIdx.y;
    int j0 = blockIdx.x * 64;
    {
        int idx = tid * 4;
        *(float4*)&Ws[idx >> 5][idx & 31] = *(const float4*)&W[idx];
    }
    #pragma unroll
    for (int q = 0; q < 2; q++) {
        int t = tid + q * 256;
        int r = t >> 3, c4 = t & 7;
        float4 v = make_float4(0.f, 0.f, 0.f, 0.f);
        if (j0 + r < NN)
            v = *(const float4*)&X[((size_t)by * NN + j0 + r) * 32 + c4 * 4];
        *(float4*)&Vs[r][c4 * 4] = v;
    }
    __syncthreads();

    int h = tid & 31;
    int rg = tid >> 5;  // 8 consecutive rows: j0 + rg*8 + r
    float acc[8];
    #pragma unroll
    for (int r = 0; r < 8; r++) acc[r] = 0.f;
    #pragma unroll 8
    for (int k = 0; k < 32; k++) {
        float w = Ws[k][h];
        #pragma unroll
        for (int r = 0; r < 8; r++) acc[r] += Vs[rg * 8 + r][k] * w;
    }
    // transposed store: 8 consecutive j for fixed h -> one uint4 per hi/lo
    if (j0 + rg * 8 < NN) {  // NN%8==0 -> full or none
        uint4 hv, lv;
        split2(acc[0], acc[1], hv.x, lv.x);
        split2(acc[2], acc[3], hv.y, lv.y);
        split2(acc[4], acc[5], hv.z, lv.z);
        split2(acc[6], acc[7], hv.w, lv.w);
        size_t o = (size_t)by * HH * NN + (size_t)h * NN + j0 + rg * 8;
        *(uint4*)(Oh + o) = hv;
        *(uint4*)(Ol + o) = lv;
    }
}

// ---------------------------------------------------------------------------
// k_gcn: C = relu(adj @ X) via mma.sync split-precision bf16.
// EXACT R7 structure (measured 139.6us/layer, 301.8us pipeline).
//   STOREY=true : write C (fp32, [b][j][h]) to Y.
//   STOREY=false: write sum_h C to s.
// CTA: 128 rows x 32 cols; 8 warps, each m16 x n32. K chunks of 64.
// ---------------------------------------------------------------------------
#define XS_STRIDE 72  // elements; 144B row stride -> conflict-free LDS + STS

template <bool STOREY>
__global__ __launch_bounds__(256) void k_gcn(const float* __restrict__ adj,
                                             const __nv_bfloat16* __restrict__ Xth,
                                             const __nv_bfloat16* __restrict__ Xtl,
                                             float* __restrict__ Y,
                                             float* __restrict__ s) {
    __shared__ __nv_bfloat16 Xs[2][32][XS_STRIDE];

    int tid = threadIdx.x, wid = tid >> 5, lane = tid & 31;
    int lq = lane & 3, lg = lane >> 2;
    int b = blockIdx.y;
    int i0 = blockIdx.x * 128;

    const float* __restrict__ adjb = adj + (size_t)b * NN * NN;
    const __nv_bfloat16* __restrict__ Xh = Xth + (size_t)b * HH * NN;
    const __nv_bfloat16* __restrict__ Xl = Xtl + (size_t)b * HH * NN;

    int mr0 = i0 + wid * 16 + lg;
    int mr1 = mr0 + 8;
    bool rv0 = mr0 < NN, rv1 = mr1 < NN;
    const float* __restrict__ ar0 = adjb + (size_t)mr0 * NN;
    const float* __restrict__ ar1 = adjb + (size_t)mr1 * NN;

    float acc[4][4];
    #pragma unroll
    for (int nt = 0; nt < 4; nt++)
        #pragma unroll
        for (int e = 0; e < 4; e++) acc[nt][e] = 0.f;

    int bh_ = tid >> 3;   // h row 0..31
    int bseg = tid & 7;   // 8-elem segment along j

    for (int c = 0; c < 32; c++) {
        int j0 = c * 64;
        __syncthreads();  // WAR: previous chunk's LDS done before overwrite
        {   // load X chunk [32 h][64 j] hi+lo into smem (uint4, conflict-free)
            int j = j0 + bseg * 8;
            uint4 vh = make_uint4(0, 0, 0, 0), vl = make_uint4(0, 0, 0, 0);
            if (j + 8 <= NN) {
                size_t o = (size_t)bh_ * NN + j;
                vh = *(const uint4*)(Xh + o);
                vl = *(const uint4*)(Xl + o);
            }
            *(uint4*)&Xs[0][bh_][bseg * 8] = vh;
            *(uint4*)&Xs[1][bh_][bseg * 8] = vl;
        }
        __syncthreads();

        if (j0 + 64 <= NN) {
            #pragma unroll
            for (int ks = 0; ks < 4; ks++) {
                int ca = j0 + ks * 16 + lq * 2;
                uint32_t ah[4], al[4];
                float2 f;
                f = rv0 ? *(const float2*)(ar0 + ca) : make_float2(0.f, 0.f);
                split2(f.x, f.y, ah[0], al[0]);
                f = rv1 ? *(const float2*)(ar1 + ca) : make_float2(0.f, 0.f);
                split2(f.x, f.y, ah[1], al[1]);
                f = rv0 ? *(const float2*)(ar0 + ca + 8) : make_float2(0.f, 0.f);
                split2(f.x, f.y, ah[2], al[2]);
                f = rv1 ? *(const float2*)(ar1 + ca + 8) : make_float2(0.f, 0.f);
                split2(f.x, f.y, ah[3], al[3]);

                int kk = ks * 16 + lq * 2;
                #pragma unroll
                for (int nt = 0; nt < 4; nt++) {
                    int n = nt * 8 + lg;
                    uint32_t bh2[2], bl2[2];
                    bh2[0] = *(const uint32_t*)&Xs[0][n][kk];
                    bh2[1] = *(const uint32_t*)&Xs[0][n][kk + 8];
                    bl2[0] = *(const uint32_t*)&Xs[1][n][kk];
                    bl2[1] = *(const uint32_t*)&Xs[1][n][kk + 8];
                    mma16816(acc[nt], ah, bh2);
                    mma16816(acc[nt], ah, bl2);
                    mma16816(acc[nt], al, bh2);
                }
            }
        } else {
            // last chunk: j0=1984, only k-step 0 (cols 1984..1999) is valid
            int ca = j0 + lq * 2;
            uint32_t ah[4], al[4];
            float2 f;
            f = rv0 ? *(const float2*)(ar0 + ca) : make_float2(0.f, 0.f);
            split2(f.x, f.y, ah[0], al[0]);
            f = rv1 ? *(const float2*)(ar1 + ca) : make_float2(0.f, 0.f);
            split2(f.x, f.y, ah[1], al[1]);
            f = rv0 ? *(const float2*)(ar0 + ca + 8) : make_float2(0.f, 0.f);
            split2(f.x, f.y, ah[2], al[2]);
            f = rv1 ? *(const float2*)(ar1 + ca + 8) : make_float2(0.f, 0.f);
            split2(f.x, f.y, ah[3], al[3]);

            int kk = lq * 2;
            #pragma unroll
            for (int nt = 0; nt < 4; nt++) {
                int n = nt * 8 + lg;
                uint32_t bh2[2], bl2[2];
                bh2[0] = *(const uint32_t*)&Xs[0][n][kk];
                bh2[1] = *(const uint32_t*)&Xs[0][n][kk + 8];
                bl2[0] = *(const uint32_t*)&Xs[1][n][kk];
                bl2[1] = *(const uint32_t*)&Xs[1][n][kk + 8];
                mma16816(acc[nt], ah, bh2);
                mma16816(acc[nt], ah, bl2);
                mma16816(acc[nt], al, bh2);
            }
        }
    }

    // ---- epilogue ----
    if (STOREY) {
        #pragma unroll
        for (int nt = 0; nt < 4; nt++) {
            int colb = nt * 8 + lq * 2;
            if (rv0) {
                float2 o = make_float2(fmaxf(acc[nt][0], 0.f), fmaxf(acc[nt][1], 0.f));
                *(float2*)&Y[((size_t)b * NN + mr0) * HH + colb] = o;
            }
            if (rv1) {
                float2 o = make_float2(fmaxf(acc[nt][2], 0.f), fmaxf(acc[nt][3], 0.f));
                *(float2*)&Y[((size_t)b * NN + mr1) * HH + colb] = o;
            }
        }
    } else {
        float s0 = 0.f, s1 = 0.f;
        #pragma unroll
        for (int nt = 0; nt < 4; nt++) {
            s0 += fmaxf(acc[nt][0], 0.f) + fmaxf(acc[nt][1], 0.f);
            s1 += fmaxf(acc[nt][2], 0.f) + fmaxf(acc[nt][3], 0.f);
        }
        s0 += __shfl_xor_sync(0xffffffffu, s0, 1);
        s0 += __shfl_xor_sync(0xffffffffu, s0, 2);
        s1 += __shfl_xor_sync(0xffffffffu, s1, 1);
        s1 += __shfl_xor_sync(0xffffffffu, s1, 2);
        if (lq == 0) {
            if (rv0) s[(size_t)b * NN + mr0] = s0;
            if (rv1) s[(size_t)b * NN + mr1] = s1;
        }
    }
}

// ---------------------------------------------------------------------------
// k_head: one CTA per (b, l); 128 threads block-reduce the 2000-dot.
// (validated 6.6us across R12-R14, vs 11.6us for the 32-CTA version)
// ---------------------------------------------------------------------------
__global__ __launch_bounds__(128) void k_head(const float* __restrict__ s,
                                              const float* __restrict__ out_w,
                                              const float* __restrict__ out_b,
                                              float* __restrict__ out) {
    __shared__ float red[4];
    int b = blockIdx.x / LL;
    int l = blockIdx.x % LL;
    int tid = threadIdx.x, lane = tid & 31, wrp = tid >> 5;
    const float* sb = s + (size_t)b * NN;
    const float* wl = out_w + (size_t)l * NN;
    float acc = 0.f;
    #pragma unroll 4
    for (int i = tid * 4; i < NN; i += 512) {
        float4 a = *(const float4*)(sb + i);
        float4 w = *(const float4*)(wl + i);
        acc += a.x * w.x + a.y * w.y + a.z * w.z + a.w * w.w;
    }
    #pragma unroll
    for (int off = 16; off > 0; off >>= 1)
        acc += __shfl_down_sync(0xffffffffu, acc, off);
    if (lane == 0) red[wrp] = acc;
    __syncthreads();
    if (tid == 0)
        out[b * LL + l] = red[0] + red[1] + red[2] + red[3] + out_b[l];
}

// ---------------------------------------------------------------------------
extern "C" void kernel_launch(void* const* d_in, const int* in_sizes, int n_in,
                              void* d_out, int out_size) {
    const float* v     = (const float*)d_in[0];
    const float* adj   = (const float*)d_in[1];
    const float* W1    = (const float*)d_in[2];
    const float* W2    = (const float*)d_in[3];
    const float* out_w = (const float*)d_in[4];
    const float* out_b = (const float*)d_in[5];
    float* out = (float*)d_out;

    __nv_bfloat16 *pX1h, *pX1l, *pX2h, *pX2l;
    float *pY1, *ps;
    cudaGetSymbolAddress((void**)&pX1h, g_X1h);
    cudaGetSymbolAddress((void**)&pX1l, g_X1l);
    cudaGetSymbolAddress((void**)&pX2h, g_X2h);
    cudaGetSymbolAddress((void**)&pX2l, g_X2l);
    cudaGetSymbolAddress((void**)&pY1, g_Y1);
    cudaGetSymbolAddress((void**)&ps, g_s);

    dim3 gridP(32, BB);   // 32 x 64-row tiles per batch
    dim3 gridG(16, BB);   // 16 x 128-row tiles per batch

    k_prep<<<gridP, 256>>>(v, W1, pX1h, pX1l);
    k_gcn<true><<<gridG, 256>>>(adj, pX1h, pX1l, pY1, nullptr);
    k_prep<<<gridP, 256>>>(pY1, W2, pX2h, pX2l);
    k_gcn<false><<<gridG, 256>>>(adj, pX2h, pX2l, nullptr, ps);
    k_head<<<BB * LL, 128>>>(ps, out_w, out_b, out);
}